// round 10
// baseline (speedup 1.0000x reference)
#include <cuda_runtime.h>
#include <math.h>
#include <stdint.h>

#define THREADS 256
#define NBATCH 4
#define BPB 148                     // CTAs per batch -> 592 total = 4/SM, 1 wave
#define NELEM (192*192*192)         // 7,077,888 per batch
#define NVEC (NELEM/4)              // 1,769,472 float4 per batch
#define CHUNK_F4 256                // float4 per tensor per stage (1 per thread)
#define CHUNK_BYTES (CHUNK_F4*16)   // 4096 B
#define CPB (NVEC/CHUNK_F4)         // 6912 chunks per batch (exact)
#define NSTAGE 6
#define STAGE_BYTES (2*CHUNK_BYTES) // 8192 B (I tile + J tile)
#define SMEM_BUF (NSTAGE*STAGE_BYTES)   // 49152 B
#define SMEM_TOTAL (SMEM_BUF + 128)     // + mbarriers (full[6], empty[6])

__device__ float g_partials[NBATCH * BPB * 5];
__device__ unsigned int g_ticket[NBATCH];   // zero-init; reset by last block

__device__ __forceinline__ uint32_t smem_u32(const void* p) {
    uint32_t a;
    asm("{ .reg .u64 t; cvta.to.shared.u64 t, %1; cvt.u32.u64 %0, t; }"
        : "=r"(a) : "l"(p));
    return a;
}

__device__ __forceinline__ float warp_sum(float v) {
    #pragma unroll
    for (int o = 16; o > 0; o >>= 1)
        v += __shfl_xor_sync(0xFFFFFFFFu, v, o);
    return v;
}

__device__ __forceinline__ void mbar_init(uint32_t m, uint32_t cnt) {
    asm volatile("mbarrier.init.shared.b64 [%0], %1;" :: "r"(m), "r"(cnt) : "memory");
}
__device__ __forceinline__ void mbar_arrive(uint32_t m) {
    asm volatile("mbarrier.arrive.shared.b64 _, [%0];" :: "r"(m) : "memory");
}
__device__ __forceinline__ void mbar_expect_tx(uint32_t m, uint32_t bytes) {
    asm volatile("mbarrier.arrive.expect_tx.shared.b64 _, [%0], %1;"
                 :: "r"(m), "r"(bytes) : "memory");
}
__device__ __forceinline__ void mbar_wait(uint32_t m, uint32_t parity) {
    uint32_t done;
    asm volatile(
        "{\n\t.reg .pred p;\n\t"
        "mbarrier.try_wait.parity.acquire.cta.shared::cta.b64 p, [%1], %2;\n\t"
        "selp.b32 %0, 1, 0, p;\n\t}"
        : "=r"(done) : "r"(m), "r"(parity) : "memory");
    if (!done) {
        asm volatile(
            "{\n\t.reg .pred P1;\n\t"
            "W_%=:\n\t"
            "mbarrier.try_wait.parity.acquire.cta.shared::cta.b64 P1, [%0], %1, 0x989680;\n\t"
            "@P1 bra.uni D_%=;\n\t"
            "bra.uni W_%=;\n\t"
            "D_%=:\n\t}"
            :: "r"(m), "r"(parity) : "memory");
    }
}
__device__ __forceinline__ void bulk_g2s(uint32_t dst, const void* src,
                                         uint32_t bytes, uint32_t mbar) {
    asm volatile(
        "cp.async.bulk.shared::cluster.global.mbarrier::complete_tx::bytes "
        "[%0], [%1], %2, [%3];"
        :: "r"(dst), "l"(src), "r"(bytes), "r"(mbar) : "memory");
}

__global__ __launch_bounds__(THREADS)
void ncc_tma(const float* __restrict__ Jg,   // y_pred
             const float* __restrict__ Ig,   // y_true
             float* __restrict__ out)
{
    extern __shared__ char smem[];
    const uint32_t smem_base = smem_u32(smem);
    const uint32_t mb_full  = smem_base + SMEM_BUF;          // 6 x 8B
    const uint32_t mb_empty = smem_base + SMEM_BUF + 64;     // 6 x 8B

    const int tid = threadIdx.x;
    const int lane = tid & 31;
    const int x = blockIdx.x;       // CTA within batch
    const int b = blockIdx.y;       // batch

    // contiguous chunk range for this CTA (46 or 47 chunks)
    const int cb  = (x * CPB) / BPB;
    const int ce  = ((x + 1) * CPB) / BPB;
    const int nit = ce - cb;

    const char* Isrc = (const char*)Ig + ((size_t)b * NVEC + (size_t)cb * CHUNK_F4) * 16;
    const char* Jsrc = (const char*)Jg + ((size_t)b * NVEC + (size_t)cb * CHUNK_F4) * 16;

    if (tid == 0) {
        #pragma unroll
        for (int s = 0; s < NSTAGE; s++) {
            mbar_init(mb_full  + 8u * s, 1);               // tx-based
            mbar_init(mb_empty + 8u * s, THREADS / 32);    // one arrive per warp
        }
    }
    __syncthreads();

    // prologue: fill the ring
    if (tid == 0) {
        const int np = nit < NSTAGE ? nit : NSTAGE;
        for (int s = 0; s < np; s++) {
            mbar_expect_tx(mb_full + 8u * s, STAGE_BYTES);
            bulk_g2s(smem_base + s * STAGE_BYTES,
                     Isrc + (size_t)s * CHUNK_BYTES, CHUNK_BYTES, mb_full + 8u * s);
            bulk_g2s(smem_base + s * STAGE_BYTES + CHUNK_BYTES,
                     Jsrc + (size_t)s * CHUNK_BYTES, CHUNK_BYTES, mb_full + 8u * s);
        }
    }

    float sI = 0.f, sJ = 0.f, sII = 0.f, sJJ = 0.f, sIJ = 0.f;

    for (int k = 0; k < nit; k++) {
        const int slot = k % NSTAGE;
        const uint32_t ph = (uint32_t)(k / NSTAGE) & 1u;
        mbar_wait(mb_full + 8u * slot, ph);

        const float4* bI = (const float4*)(smem + slot * STAGE_BYTES);
        const float4* bJ = (const float4*)(smem + slot * STAGE_BYTES + CHUNK_BYTES);
        float4 a = bI[tid];
        float4 c = bJ[tid];

        sI  += a.x + a.y + a.z + a.w;
        sII += a.x*a.x + a.y*a.y + a.z*a.z + a.w*a.w;
        sJ  += c.x + c.y + c.z + c.w;
        sJJ += c.x*c.x + c.y*c.y + c.z*c.z + c.w*c.w;
        sIJ += a.x*c.x + a.y*c.y + a.z*c.z + a.w*c.w;

        if (lane == 0) mbar_arrive(mb_empty + 8u * slot);   // warp done with slot

        if (tid == 0 && k + NSTAGE < nit) {
            const int kn = k + NSTAGE;
            // slot reusable once all 8 warps of round k arrived
            mbar_wait(mb_empty + 8u * slot, ph);
            mbar_expect_tx(mb_full + 8u * slot, STAGE_BYTES);
            bulk_g2s(smem_base + slot * STAGE_BYTES,
                     Isrc + (size_t)kn * CHUNK_BYTES, CHUNK_BYTES, mb_full + 8u * slot);
            bulk_g2s(smem_base + slot * STAGE_BYTES + CHUNK_BYTES,
                     Jsrc + (size_t)kn * CHUNK_BYTES, CHUNK_BYTES, mb_full + 8u * slot);
        }
    }

    // ---- block reduce ----
    sI  = warp_sum(sI);
    sJ  = warp_sum(sJ);
    sII = warp_sum(sII);
    sJJ = warp_sum(sJJ);
    sIJ = warp_sum(sIJ);

    __shared__ float sm[5][THREADS / 32];
    __shared__ bool isLast;
    const int wid = tid >> 5;
    if (lane == 0) {
        sm[0][wid] = sI;  sm[1][wid] = sJ;  sm[2][wid] = sII;
        sm[3][wid] = sJJ; sm[4][wid] = sIJ;
    }
    __syncthreads();

    if (wid == 0) {
        const int nw = THREADS / 32;
        float v0 = (lane < nw) ? sm[0][lane] : 0.f;
        float v1 = (lane < nw) ? sm[1][lane] : 0.f;
        float v2 = (lane < nw) ? sm[2][lane] : 0.f;
        float v3 = (lane < nw) ? sm[3][lane] : 0.f;
        float v4 = (lane < nw) ? sm[4][lane] : 0.f;
        v0 = warp_sum(v0); v1 = warp_sum(v1); v2 = warp_sum(v2);
        v3 = warp_sum(v3); v4 = warp_sum(v4);
        if (lane == 0) {
            float* p = &g_partials[(b * BPB + x) * 5];
            p[0] = v0; p[1] = v1; p[2] = v2; p[3] = v3; p[4] = v4;
            __threadfence();
            unsigned int t = atomicAdd(&g_ticket[b], 1u);
            isLast = (t == BPB - 1);
        }
    }
    __syncthreads();

    if (!isLast) return;

    // ---- last block of this batch: final reduce ----
    float tI = 0.f, tJ = 0.f, tII = 0.f, tJJ = 0.f, tIJ = 0.f;
    for (int i = tid; i < BPB; i += THREADS) {
        const float* p = &g_partials[(b * BPB + i) * 5];
        tI += p[0]; tJ += p[1]; tII += p[2]; tJJ += p[3]; tIJ += p[4];
    }
    tI  = warp_sum(tI);
    tJ  = warp_sum(tJ);
    tII = warp_sum(tII);
    tJJ = warp_sum(tJJ);
    tIJ = warp_sum(tIJ);

    __syncthreads();
    if (lane == 0) {
        sm[0][wid] = tI;  sm[1][wid] = tJ;  sm[2][wid] = tII;
        sm[3][wid] = tJJ; sm[4][wid] = tIJ;
    }
    __syncthreads();

    if (tid == 0) {
        const int nw = THREADS / 32;
        float fI = 0.f, fJ = 0.f, fII = 0.f, fJJ = 0.f, fIJ = 0.f;
        for (int w = 0; w < nw; w++) {
            fI += sm[0][w]; fJ += sm[1][w]; fII += sm[2][w];
            fJJ += sm[3][w]; fIJ += sm[4][w];
        }
        const float n = (float)NELEM;
        float cross = fIJ - fI * fJ / n;
        float Ivar  = fII - fI * fI / n;
        float Jvar  = fJJ - fJ * fJ / n;
        out[b] = cross / (sqrtf(Ivar) * sqrtf(Jvar) + 1e-5f);
        g_ticket[b] = 0u;   // reset for next graph replay
    }
}

extern "C" void kernel_launch(void* const* d_in, const int* in_sizes, int n_in,
                              void* d_out, int out_size)
{
    const float* y_pred = (const float*)d_in[0];  // Ji
    const float* y_true = (const float*)d_in[1];  // Ii
    float* out = (float*)d_out;

    cudaFuncSetAttribute(ncc_tma, cudaFuncAttributeMaxDynamicSharedMemorySize,
                         SMEM_TOTAL);
    dim3 grid(BPB, NBATCH);
    ncc_tma<<<grid, THREADS, SMEM_TOTAL>>>(y_pred, y_true, out);
}

// round 11
// speedup vs baseline: 1.0073x; 1.0073x over previous
#include <cuda_runtime.h>
#include <math.h>

#define BPB 256            // blocks per batch; 1024 CTAs ~7/SM single wave
#define THREADS 256
#define NBATCH 4
#define NELEM (192*192*192)        // 7,077,888 per batch
#define NVEC  (NELEM/4)            // 1,769,472 float4 per batch
// NVEC / (BPB*THREADS) = 27 exactly -> no tail iteration

__device__ float g_partials[NBATCH * BPB * 5];
__device__ unsigned int g_ticket[NBATCH];   // zero-init; reset by last block each run

__device__ __forceinline__ float warp_sum(float v) {
    #pragma unroll
    for (int o = 16; o > 0; o >>= 1)
        v += __shfl_xor_sync(0xFFFFFFFFu, v, o);
    return v;
}

__global__ __launch_bounds__(THREADS, 8)   // <=32 regs -> 64 warps/SM
void ncc_fused(const float4* __restrict__ J4,   // y_pred
               const float4* __restrict__ I4,   // y_true
               float* __restrict__ out)
{
    const int b = blockIdx.y;
    const float4* __restrict__ Ib = I4 + (size_t)b * NVEC;
    const float4* __restrict__ Jb = J4 + (size_t)b * NVEC;

    float sI = 0.f, sJ = 0.f, sII = 0.f, sJJ = 0.f, sIJ = 0.f;

    for (int i = blockIdx.x * THREADS + threadIdx.x; i < NVEC;
         i += BPB * THREADS) {
        float4 a = Ib[i];
        float4 c = Jb[i];
        sI  += a.x + a.y + a.z + a.w;
        sJ  += c.x + c.y + c.z + c.w;
        sII += a.x*a.x + a.y*a.y + a.z*a.z + a.w*a.w;
        sJJ += c.x*c.x + c.y*c.y + c.z*c.z + c.w*c.w;
        sIJ += a.x*c.x + a.y*c.y + a.z*c.z + a.w*c.w;
    }

    // intra-warp reduce
    sI  = warp_sum(sI);
    sJ  = warp_sum(sJ);
    sII = warp_sum(sII);
    sJJ = warp_sum(sJJ);
    sIJ = warp_sum(sIJ);

    __shared__ float sm[5][THREADS / 32];
    const int lane = threadIdx.x & 31;
    const int wid  = threadIdx.x >> 5;
    if (lane == 0) {
        sm[0][wid] = sI;  sm[1][wid] = sJ;  sm[2][wid] = sII;
        sm[3][wid] = sJJ; sm[4][wid] = sIJ;
    }
    __syncthreads();

    __shared__ bool isLast;
    if (wid == 0) {
        const int nw = THREADS / 32;
        float v0 = (lane < nw) ? sm[0][lane] : 0.f;
        float v1 = (lane < nw) ? sm[1][lane] : 0.f;
        float v2 = (lane < nw) ? sm[2][lane] : 0.f;
        float v3 = (lane < nw) ? sm[3][lane] : 0.f;
        float v4 = (lane < nw) ? sm[4][lane] : 0.f;
        v0 = warp_sum(v0); v1 = warp_sum(v1); v2 = warp_sum(v2);
        v3 = warp_sum(v3); v4 = warp_sum(v4);
        if (lane == 0) {
            float* p = &g_partials[(b * BPB + blockIdx.x) * 5];
            p[0] = v0; p[1] = v1; p[2] = v2; p[3] = v3; p[4] = v4;
            __threadfence();
            unsigned int t = atomicAdd(&g_ticket[b], 1u);
            isLast = (t == BPB - 1);
        }
    }
    __syncthreads();

    if (!isLast) return;

    // ---- last block for this batch: exactly one round over BPB=256 partials ----
    {
        const float* p = &g_partials[(b * BPB + threadIdx.x) * 5];
        float tI  = p[0];
        float tJ  = p[1];
        float tII = p[2];
        float tJJ = p[3];
        float tIJ = p[4];

        tI  = warp_sum(tI);
        tJ  = warp_sum(tJ);
        tII = warp_sum(tII);
        tJJ = warp_sum(tJJ);
        tIJ = warp_sum(tIJ);

        __syncthreads();   // sm[][] reuse
        if (lane == 0) {
            sm[0][wid] = tI;  sm[1][wid] = tJ;  sm[2][wid] = tII;
            sm[3][wid] = tJJ; sm[4][wid] = tIJ;
        }
        __syncthreads();

        if (threadIdx.x == 0) {
            const int nw = THREADS / 32;
            float fI = 0.f, fJ = 0.f, fII = 0.f, fJJ = 0.f, fIJ = 0.f;
            for (int w = 0; w < nw; w++) {
                fI += sm[0][w]; fJ += sm[1][w]; fII += sm[2][w];
                fJJ += sm[3][w]; fIJ += sm[4][w];
            }
            const float n = (float)NELEM;
            float cross = fIJ - fI * fJ / n;
            float Ivar  = fII - fI * fI / n;
            float Jvar  = fJJ - fJ * fJ / n;
            out[b] = cross / (sqrtf(Ivar) * sqrtf(Jvar) + 1e-5f);
            g_ticket[b] = 0u;    // reset for next graph replay
        }
    }
}

extern "C" void kernel_launch(void* const* d_in, const int* in_sizes, int n_in,
                              void* d_out, int out_size)
{
    const float4* y_pred = (const float4*)d_in[0];  // Ji
    const float4* y_true = (const float4*)d_in[1];  // Ii
    float* out = (float*)d_out;

    dim3 grid(BPB, NBATCH);
    ncc_fused<<<grid, THREADS>>>(y_pred, y_true, out);
}